// round 1
// baseline (speedup 1.0000x reference)
#include <cuda_runtime.h>
#include <cuda_bf16.h>
#include <mma.h>
#include <math.h>

using namespace nvcuda;

// Problem constants (fixed by the dataset)
#define B_    16
#define NT_   64
#define T_    8
#define D_    25088
#define C_    1000
#define M_    (B_ * NT_)   // 1024 rows (b, tube)
#define NPAD  1024         // padded class dim
#define K_    D_

// ---------------- scratch (no allocations allowed) ----------------
__device__ float g_pooled[(size_t)M_ * D_];     // ~103 MB
__device__ float g_logits[(size_t)M_ * NPAD];   // 4 MB
__device__ float g_row_nll[M_];
__device__ int   g_row_valid[M_];

// ---------------- kernel 1: masked temporal mean pooling ----------------
// pooled[m, d] = (1/len[b]) * sum_{t < len[b]} features[b, n, t, d]
__global__ __launch_bounds__(256) void pool_kernel(const float* __restrict__ feats,
                                                   const int* __restrict__ lens) {
    int m = blockIdx.x;            // m = b*NT_ + n
    int b = m / NT_;
    int len = lens[b];             // 1..T_
    float inv = 1.0f / (float)len;

    const float4* base = (const float4*)(feats + (size_t)m * T_ * D_);
    float4* out = (float4*)(g_pooled + (size_t)m * D_);
    const int nv = D_ / 4;         // 6272

    for (int i = threadIdx.x; i < nv; i += blockDim.x) {
        float4 acc = make_float4(0.f, 0.f, 0.f, 0.f);
        #pragma unroll
        for (int t = 0; t < T_; ++t) {
            if (t < len) {
                float4 v = base[(size_t)t * (D_ / 4) + i];
                acc.x += v.x; acc.y += v.y; acc.z += v.z; acc.w += v.w;
            }
        }
        acc.x *= inv; acc.y *= inv; acc.z *= inv; acc.w *= inv;
        out[i] = acc;
    }
}

// ---------------- kernel 2: tf32 WMMA GEMM ----------------
// logits[m, c] = sum_d pooled[m, d] * W[c, d]   (bias added later)
// Block tile 64x64, K-chunk 16. 4 warps, each computes 32x32 via 2x2 m16n16k8 frags.
#define BM 64
#define BN 64
#define BK 16

__global__ __launch_bounds__(128) void gemm_kernel(const float* __restrict__ Wmat) {
    __shared__ float As[BM * BK];   // A row-major: (m,k) at m*BK + k
    __shared__ float Bs[BN * BK];   // B col-major: (k,n) at n*BK + k  (n indexes class)

    const int bm = blockIdx.y * BM;
    const int bn = blockIdx.x * BN;
    const int tid = threadIdx.x;            // 128 threads
    const int warp = tid >> 5;
    const int wm = (warp >> 1) * 32;        // warp row offset in tile
    const int wn = (warp & 1) * 32;         // warp col offset in tile

    wmma::fragment<wmma::accumulator, 16, 16, 8, float> acc[2][2];
    #pragma unroll
    for (int i = 0; i < 2; ++i)
        #pragma unroll
        for (int j = 0; j < 2; ++j)
            wmma::fill_fragment(acc[i][j], 0.0f);

    // Global->shared load mapping: thread t loads 8 consecutive K elements of
    // row (t>>1), at K offset (t&1)*8. 64 rows x 16 cols = 1024 floats per tile.
    const int lr = tid >> 1;
    const int lk = (tid & 1) * 8;
    const float* Ag = g_pooled + (size_t)(bm + lr) * K_ + lk;
    const bool  bvalid = (bn + lr) < C_;     // class-row bound (C_=1000 < NPAD)
    const float* Bg = Wmat + (size_t)(bn + lr) * K_ + lk;
    float* Asp = &As[lr * BK + lk];
    float* Bsp = &Bs[lr * BK + lk];

    for (int k0 = 0; k0 < K_; k0 += BK) {
        float4 a0 = *(const float4*)(Ag + k0);
        float4 a1 = *(const float4*)(Ag + k0 + 4);
        float4 b0 = make_float4(0.f, 0.f, 0.f, 0.f);
        float4 b1 = make_float4(0.f, 0.f, 0.f, 0.f);
        if (bvalid) {
            b0 = *(const float4*)(Bg + k0);
            b1 = *(const float4*)(Bg + k0 + 4);
        }
        __syncthreads();                 // previous iteration's MMAs done reading
        *(float4*)(Asp)     = a0;
        *(float4*)(Asp + 4) = a1;
        *(float4*)(Bsp)     = b0;
        *(float4*)(Bsp + 4) = b1;
        __syncthreads();

        #pragma unroll
        for (int ks = 0; ks < 2; ++ks) {  // two k=8 steps per BK=16 chunk
            wmma::fragment<wmma::matrix_a, 16, 16, 8, wmma::precision::tf32, wmma::row_major> af[2];
            wmma::fragment<wmma::matrix_b, 16, 16, 8, wmma::precision::tf32, wmma::col_major> bf[2];
            #pragma unroll
            for (int i = 0; i < 2; ++i) {
                wmma::load_matrix_sync(af[i], &As[(wm + i * 16) * BK + ks * 8], BK);
                #pragma unroll
                for (int e = 0; e < af[i].num_elements; ++e)
                    af[i].x[e] = wmma::__float_to_tf32(af[i].x[e]);
            }
            #pragma unroll
            for (int j = 0; j < 2; ++j) {
                wmma::load_matrix_sync(bf[j], &Bs[(wn + j * 16) * BK + ks * 8], BK);
                #pragma unroll
                for (int e = 0; e < bf[j].num_elements; ++e)
                    bf[j].x[e] = wmma::__float_to_tf32(bf[j].x[e]);
            }
            #pragma unroll
            for (int i = 0; i < 2; ++i)
                #pragma unroll
                for (int j = 0; j < 2; ++j)
                    wmma::mma_sync(acc[i][j], af[i], bf[j], acc[i][j]);
        }
    }

    #pragma unroll
    for (int i = 0; i < 2; ++i)
        #pragma unroll
        for (int j = 0; j < 2; ++j)
            wmma::store_matrix_sync(&g_logits[(size_t)(bm + wm + i * 16) * NPAD + bn + wn + j * 16],
                                    acc[i][j], NPAD, wmma::mem_row_major);
}

// ---------------- kernel 3: per-row log-softmax NLL ----------------
__global__ __launch_bounds__(256) void nll_kernel(const float* __restrict__ bias,
                                                  const int* __restrict__ labels) {
    const int m = blockIdx.x;
    const int tid = threadIdx.x;
    const int lbl = labels[m];
    const float* row = g_logits + (size_t)m * NPAD;

    __shared__ float red[256];

    // max
    float mx = -INFINITY;
    for (int c = tid; c < C_; c += 256) mx = fmaxf(mx, row[c] + bias[c]);
    red[tid] = mx;
    __syncthreads();
    for (int s = 128; s > 0; s >>= 1) {
        if (tid < s) red[tid] = fmaxf(red[tid], red[tid + s]);
        __syncthreads();
    }
    const float smax = red[0];
    __syncthreads();

    // sum exp
    float sum = 0.0f;
    for (int c = tid; c < C_; c += 256) sum += __expf(row[c] + bias[c] - smax);
    red[tid] = sum;
    __syncthreads();
    for (int s = 128; s > 0; s >>= 1) {
        if (tid < s) red[tid] += red[tid + s];
        __syncthreads();
    }

    if (tid == 0) {
        if (lbl >= 0) {
            float tgt = row[lbl] + bias[lbl];
            g_row_nll[m] = logf(red[0]) + smax - tgt;   // -logp[label]
            g_row_valid[m] = 1;
        } else {
            g_row_nll[m] = 0.0f;
            g_row_valid[m] = 0;
        }
    }
}

// ---------------- kernel 4: final reduction ----------------
__global__ __launch_bounds__(256) void finalize_kernel(float* __restrict__ out) {
    __shared__ float ssum[256];
    __shared__ int   scnt[256];
    const int tid = threadIdx.x;
    float s = 0.0f; int c = 0;
    for (int i = tid; i < M_; i += 256) { s += g_row_nll[i]; c += g_row_valid[i]; }
    ssum[tid] = s; scnt[tid] = c;
    __syncthreads();
    for (int st = 128; st > 0; st >>= 1) {
        if (tid < st) { ssum[tid] += ssum[tid + st]; scnt[tid] += scnt[tid + st]; }
        __syncthreads();
    }
    if (tid == 0) {
        int n = scnt[0] > 0 ? scnt[0] : 1;
        out[0] = ssum[0] / (float)n;
    }
}

// ---------------- launch ----------------
extern "C" void kernel_launch(void* const* d_in, const int* in_sizes, int n_in,
                              void* d_out, int out_size) {
    const float* feats  = (const float*)d_in[0];   // (16,64,8,25088) f32
    const float* Wmat   = (const float*)d_in[1];   // (1000,25088) f32
    const float* bias   = (const float*)d_in[2];   // (1000,) f32
    // d_in[3] = n_tubes (scalar int, always 64 here)
    const int*   target = (const int*)d_in[4];     // (16,64) int32
    const int*   lens   = (const int*)d_in[5];     // (16,1,1) int32

    pool_kernel<<<M_, 256>>>(feats, lens);

    dim3 grid(NPAD / BN, M_ / BM);   // (16, 16) = 256 CTAs
    gemm_kernel<<<grid, 128>>>(Wmat);

    nll_kernel<<<M_, 256>>>(bias, target);
    finalize_kernel<<<1, 256>>>((float*)d_out);
}

// round 3
// speedup vs baseline: 2.0357x; 2.0357x over previous
#include <cuda_runtime.h>
#include <cuda_bf16.h>
#include <mma.h>
#include <math.h>
#include <cstdint>
#include <cstddef>

using namespace nvcuda;

// Problem constants (fixed by the dataset)
#define B_    16
#define NT_   64
#define T_    8
#define D_    25088
#define C_    1000
#define M_    (B_ * NT_)   // 1024 rows
#define NPAD  1024         // padded class dim
#define K_    D_

// GEMM tiling
#define BM     128
#define BN     128
#define BKK    32
#define STAGES 3
#define SPLITS 4
#define KSPLIT (K_ / SPLITS)     // 6272
#define NIT    (KSPLIT / BKK)    // 196
#define S_LD   36                // padded smem row stride (floats)
#define STAGE_FLOATS ((BM + BN) * S_LD)          // 9216
#define SMEM_BYTES   (STAGES * STAGE_FLOATS * 4) // 110592

// ---------------- scratch ----------------
__device__ float g_pooled[(size_t)M_ * D_];              // 103 MB
__device__ float g_part[(size_t)SPLITS * M_ * NPAD];     // 16 MB
__device__ float g_logits[(size_t)M_ * NPAD];            // 4 MB
__device__ float g_row_nll[M_];
__device__ int   g_row_valid[M_];

// ---------------- kernel 1: masked temporal mean pooling ----------------
__global__ __launch_bounds__(256) void pool_kernel(const float* __restrict__ feats,
                                                   const int* __restrict__ lens) {
    int m = blockIdx.x;            // m = b*NT_ + n
    int b = m / NT_;
    int len = lens[b];             // 1..T_
    float inv = 1.0f / (float)len;

    const float4* base = (const float4*)(feats + (size_t)m * T_ * D_);
    float4* out = (float4*)(g_pooled + (size_t)m * D_);
    const int nv = D_ / 4;         // 6272

    for (int i = threadIdx.x; i < nv; i += blockDim.x) {
        float4 acc = make_float4(0.f, 0.f, 0.f, 0.f);
        #pragma unroll
        for (int t = 0; t < T_; ++t) {
            if (t < len) {
                float4 v = base[(size_t)t * (D_ / 4) + i];
                acc.x += v.x; acc.y += v.y; acc.z += v.z; acc.w += v.w;
            }
        }
        acc.x *= inv; acc.y *= inv; acc.z *= inv; acc.w *= inv;
        out[i] = acc;
    }
}

// ---------------- kernel 2: pipelined tf32 WMMA GEMM (split-K) ----------------
__device__ __forceinline__ void cp16(unsigned smem_dst, const void* gsrc, int src_sz) {
    asm volatile("cp.async.cg.shared.global [%0], [%1], 16, %2;\n"
                 :: "r"(smem_dst), "l"(gsrc), "r"(src_sz));
}

__global__ __launch_bounds__(256) void gemm_kernel(const float* __restrict__ Wmat) {
    extern __shared__ float sh[];

    const int bn    = blockIdx.x * BN;
    const int bm    = blockIdx.y * BM;
    const int split = blockIdx.z;
    const int kbase = split * KSPLIT;
    const int tid   = threadIdx.x;
    const int warp  = tid >> 5;
    const int wm    = (warp & 3) * 32;   // 4 warps along M, warp tile 32
    const int wn    = (warp >> 2) * 64;  // 2 warps along N, warp tile 64

    wmma::fragment<wmma::accumulator, 16, 16, 8, float> acc[2][4];
    #pragma unroll
    for (int i = 0; i < 2; ++i)
        #pragma unroll
        for (int j = 0; j < 4; ++j)
            wmma::fill_fragment(acc[i][j], 0.0f);

    // per-stage loader: A tile 128x32 and B tile 128x32, each 1024 float4
    auto load_stage = [&](int stage, int k0) {
        float* As = sh + stage * STAGE_FLOATS;
        float* Bs = As + BM * S_LD;
        #pragma unroll
        for (int i = 0; i < 4; ++i) {
            int idx = tid + i * 256;
            int row = idx >> 3;
            int c   = (idx & 7) * 4;
            const float* src = g_pooled + (size_t)(bm + row) * K_ + k0 + c;
            unsigned dst = (unsigned)__cvta_generic_to_shared(As + row * S_LD + c);
            cp16(dst, src, 16);
        }
        #pragma unroll
        for (int i = 0; i < 4; ++i) {
            int idx = tid + i * 256;
            int row = idx >> 3;
            int c   = (idx & 7) * 4;
            int brow = bn + row;
            int ok   = (brow < C_);
            const float* src = Wmat + (size_t)(ok ? brow : 0) * K_ + k0 + c;
            unsigned dst = (unsigned)__cvta_generic_to_shared(Bs + row * S_LD + c);
            cp16(dst, src, ok ? 16 : 0);   // zero-fill padded class rows
        }
    };

    load_stage(0, kbase);
    asm volatile("cp.async.commit_group;\n");
    load_stage(1, kbase + BKK);
    asm volatile("cp.async.commit_group;\n");

    for (int it = 0; it < NIT; ++it) {
        if (it + 2 < NIT)
            load_stage((it + 2) % STAGES, kbase + (it + 2) * BKK);
        asm volatile("cp.async.commit_group;\n");
        asm volatile("cp.async.wait_group 2;\n");   // stage it%3 resident
        __syncthreads();

        const float* As = sh + (it % STAGES) * STAGE_FLOATS;
        const float* Bs = As + BM * S_LD;

        #pragma unroll
        for (int ks = 0; ks < BKK / 8; ++ks) {
            wmma::fragment<wmma::matrix_a, 16, 16, 8, wmma::precision::tf32, wmma::row_major> af[2];
            wmma::fragment<wmma::matrix_b, 16, 16, 8, wmma::precision::tf32, wmma::col_major> bf[4];
            #pragma unroll
            for (int i = 0; i < 2; ++i) {
                wmma::load_matrix_sync(af[i], As + (wm + i * 16) * S_LD + ks * 8, S_LD);
                #pragma unroll
                for (int e = 0; e < af[i].num_elements; ++e)
                    af[i].x[e] = wmma::__float_to_tf32(af[i].x[e]);
            }
            #pragma unroll
            for (int j = 0; j < 4; ++j) {
                wmma::load_matrix_sync(bf[j], Bs + (wn + j * 16) * S_LD + ks * 8, S_LD);
                #pragma unroll
                for (int e = 0; e < bf[j].num_elements; ++e)
                    bf[j].x[e] = wmma::__float_to_tf32(bf[j].x[e]);
            }
            #pragma unroll
            for (int i = 0; i < 2; ++i)
                #pragma unroll
                for (int j = 0; j < 4; ++j)
                    wmma::mma_sync(acc[i][j], af[i], bf[j], acc[i][j]);
        }
        __syncthreads();   // stage consumed; next iteration may overwrite it
    }

    float* base = g_part + (size_t)split * M_ * NPAD;
    #pragma unroll
    for (int i = 0; i < 2; ++i)
        #pragma unroll
        for (int j = 0; j < 4; ++j)
            wmma::store_matrix_sync(base + (size_t)(bm + wm + i * 16) * NPAD + (bn + wn + j * 16),
                                    acc[i][j], NPAD, wmma::mem_row_major);
}

// ---------------- kernel 2b: split-K reduction (fixed order, deterministic) ----
__global__ __launch_bounds__(256) void splitk_reduce() {
    const size_t idx = (size_t)blockIdx.x * 256 + threadIdx.x;  // over 262144 float4
    const float4* p = (const float4*)g_part;
    const size_t stride = (size_t)M_ * NPAD / 4;
    float4 a = p[idx];
    #pragma unroll
    for (int s = 1; s < SPLITS; ++s) {
        float4 b = p[idx + s * stride];
        a.x += b.x; a.y += b.y; a.z += b.z; a.w += b.w;
    }
    ((float4*)g_logits)[idx] = a;
}

// ---------------- kernel 3: per-row log-softmax NLL ----------------
__global__ __launch_bounds__(256) void nll_kernel(const float* __restrict__ bias,
                                                  const int* __restrict__ labels) {
    const int m = blockIdx.x;
    const int tid = threadIdx.x;
    const int lbl = labels[m];
    const float* row = g_logits + (size_t)m * NPAD;

    __shared__ float red[256];

    float mx = -INFINITY;
    for (int c = tid; c < C_; c += 256) mx = fmaxf(mx, row[c] + bias[c]);
    red[tid] = mx;
    __syncthreads();
    for (int s = 128; s > 0; s >>= 1) {
        if (tid < s) red[tid] = fmaxf(red[tid], red[tid + s]);
        __syncthreads();
    }
    const float smax = red[0];
    __syncthreads();

    float sum = 0.0f;
    for (int c = tid; c < C_; c += 256) sum += __expf(row[c] + bias[c] - smax);
    red[tid] = sum;
    __syncthreads();
    for (int s = 128; s > 0; s >>= 1) {
        if (tid < s) red[tid] += red[tid + s];
        __syncthreads();
    }

    if (tid == 0) {
        if (lbl >= 0) {
            float tgt = row[lbl] + bias[lbl];
            g_row_nll[m] = logf(red[0]) + smax - tgt;
            g_row_valid[m] = 1;
        } else {
            g_row_nll[m] = 0.0f;
            g_row_valid[m] = 0;
        }
    }
}

// ---------------- kernel 4: final reduction ----------------
__global__ __launch_bounds__(256) void finalize_kernel(float* __restrict__ out) {
    __shared__ float ssum[256];
    __shared__ int   scnt[256];
    const int tid = threadIdx.x;
    float s = 0.0f; int c = 0;
    for (int i = tid; i < M_; i += 256) { s += g_row_nll[i]; c += g_row_valid[i]; }
    ssum[tid] = s; scnt[tid] = c;
    __syncthreads();
    for (int st = 128; st > 0; st >>= 1) {
        if (tid < st) { ssum[tid] += ssum[tid + st]; scnt[tid] += scnt[tid + st]; }
        __syncthreads();
    }
    if (tid == 0) {
        int n = scnt[0] > 0 ? scnt[0] : 1;
        out[0] = ssum[0] / (float)n;
    }
}

// ---------------- launch ----------------
extern "C" void kernel_launch(void* const* d_in, const int* in_sizes, int n_in,
                              void* d_out, int out_size) {
    const float* feats  = (const float*)d_in[0];   // (16,64,8,25088) f32
    const float* Wmat   = (const float*)d_in[1];   // (1000,25088) f32
    const float* bias   = (const float*)d_in[2];   // (1000,) f32
    const int*   target = (const int*)d_in[4];     // (16,64) int32
    const int*   lens   = (const int*)d_in[5];     // (16,1,1) int32

    cudaFuncSetAttribute(gemm_kernel, cudaFuncAttributeMaxDynamicSharedMemorySize, SMEM_BYTES);

    pool_kernel<<<M_, 256>>>(feats, lens);

    dim3 grid(NPAD / BN, M_ / BM, SPLITS);   // (8, 8, 4) = 256 CTAs
    gemm_kernel<<<grid, 256, SMEM_BYTES>>>(Wmat);

    splitk_reduce<<<(M_ * NPAD / 4) / 256, 256>>>();
    nll_kernel<<<M_, 256>>>(bias, target);
    finalize_kernel<<<1, 256>>>((float*)d_out);
}

// round 4
// speedup vs baseline: 5.9576x; 2.9265x over previous
#include <cuda_runtime.h>
#include <cuda_bf16.h>
#include <mma.h>
#include <math.h>
#include <cstdint>
#include <cstddef>

using namespace nvcuda;

// Problem constants
#define B_    16
#define NT_   64
#define T_    8
#define D_    25088
#define C_    1000
#define M_    (B_ * NT_)   // 1024
#define NPAD  1024
#define K_    D_

// GEMM tiling (bf16)
#define BM     128
#define BN     128
#define BKK    32              // bf16 elements per K-chunk
#define STAGES 4
#define SPLITS 4
#define KSPLIT (K_ / SPLITS)   // 6272
#define NIT    (KSPLIT / BKK)  // 196
#define S_LDH  40              // padded smem row stride (bf16 elems) = 80B
#define STAGE_H ((BM + BN) * S_LDH)              // 10240 bf16
#define SMEM_BYTES (STAGES * STAGE_H * 2)        // 81920

// ---------------- scratch ----------------
__device__ __nv_bfloat16 g_pooled_h[(size_t)M_ * K_];   // 51 MB
__device__ __nv_bfloat16 g_W_h[(size_t)C_ * K_];        // 50 MB
__device__ float g_part[(size_t)SPLITS * M_ * NPAD];    // 16 MB
__device__ float g_row_nll[M_];
__device__ int   g_row_valid[M_];

// ---------------- kernel 1: masked mean pooling -> bf16 ----------------
__global__ __launch_bounds__(256) void pool_kernel(const float* __restrict__ feats,
                                                   const int* __restrict__ lens) {
    int m = blockIdx.x;            // m = b*NT_ + n
    int b = m / NT_;
    int len = lens[b];
    float inv = 1.0f / (float)len;

    const float4* base = (const float4*)(feats + (size_t)m * T_ * D_);
    __nv_bfloat162* out = (__nv_bfloat162*)(g_pooled_h + (size_t)m * K_);
    const int nv = D_ / 4;

    for (int i = threadIdx.x; i < nv; i += blockDim.x) {
        float4 acc = make_float4(0.f, 0.f, 0.f, 0.f);
        #pragma unroll
        for (int t = 0; t < T_; ++t) {
            if (t < len) {
                float4 v = base[(size_t)t * (D_ / 4) + i];
                acc.x += v.x; acc.y += v.y; acc.z += v.z; acc.w += v.w;
            }
        }
        out[i * 2]     = __floats2bfloat162_rn(acc.x * inv, acc.y * inv);
        out[i * 2 + 1] = __floats2bfloat162_rn(acc.z * inv, acc.w * inv);
    }
}

// ---------------- kernel 1b: W -> bf16 ----------------
__global__ __launch_bounds__(256) void convw_kernel(const float* __restrict__ W) {
    const size_t n4 = (size_t)C_ * K_ / 4;
    const float4* src = (const float4*)W;
    __nv_bfloat162* dst = (__nv_bfloat162*)g_W_h;
    for (size_t i = (size_t)blockIdx.x * 256 + threadIdx.x; i < n4;
         i += (size_t)gridDim.x * 256) {
        float4 v = src[i];
        dst[i * 2]     = __floats2bfloat162_rn(v.x, v.y);
        dst[i * 2 + 1] = __floats2bfloat162_rn(v.z, v.w);
    }
}

// ---------------- kernel 2: pipelined bf16 WMMA GEMM (split-K) ----------------
__device__ __forceinline__ void cp16(unsigned smem_dst, const void* gsrc, int src_sz) {
    asm volatile("cp.async.cg.shared.global [%0], [%1], 16, %2;\n"
                 :: "r"(smem_dst), "l"(gsrc), "r"(src_sz));
}

__global__ __launch_bounds__(256, 2) void gemm_kernel() {
    extern __shared__ __nv_bfloat16 sh[];

    const int bn    = blockIdx.x * BN;
    const int bm    = blockIdx.y * BM;
    const int split = blockIdx.z;
    const int kbase = split * KSPLIT;
    const int tid   = threadIdx.x;
    const int warp  = tid >> 5;
    const int wm    = (warp & 3) * 32;   // 4 warps along M
    const int wn    = (warp >> 2) * 64;  // 2 warps along N

    wmma::fragment<wmma::accumulator, 16, 16, 16, float> acc[2][4];
    #pragma unroll
    for (int i = 0; i < 2; ++i)
        #pragma unroll
        for (int j = 0; j < 4; ++j)
            wmma::fill_fragment(acc[i][j], 0.0f);

    // stage loader: A 128x32 bf16 + B 128x32 bf16; 16B = 8 elems, 4 chunks/row
    auto load_stage = [&](int stage, int k0) {
        __nv_bfloat16* As = sh + stage * STAGE_H;
        __nv_bfloat16* Bs = As + BM * S_LDH;
        #pragma unroll
        for (int i = 0; i < 2; ++i) {
            int idx = tid + i * 256;
            int row = idx >> 2;
            int c   = (idx & 3) * 8;
            const __nv_bfloat16* src = g_pooled_h + (size_t)(bm + row) * K_ + k0 + c;
            unsigned dst = (unsigned)__cvta_generic_to_shared(As + row * S_LDH + c);
            cp16(dst, src, 16);
        }
        #pragma unroll
        for (int i = 0; i < 2; ++i) {
            int idx = tid + i * 256;
            int row = idx >> 2;
            int c   = (idx & 3) * 8;
            int brow = bn + row;
            int ok   = (brow < C_);
            const __nv_bfloat16* src = g_W_h + (size_t)(ok ? brow : 0) * K_ + k0 + c;
            unsigned dst = (unsigned)__cvta_generic_to_shared(Bs + row * S_LDH + c);
            cp16(dst, src, ok ? 16 : 0);   // zero-fill padded class rows
        }
    };

    load_stage(0, kbase);
    asm volatile("cp.async.commit_group;\n");
    load_stage(1, kbase + BKK);
    asm volatile("cp.async.commit_group;\n");
    load_stage(2, kbase + 2 * BKK);
    asm volatile("cp.async.commit_group;\n");

    for (int it = 0; it < NIT; ++it) {
        if (it + 3 < NIT)
            load_stage((it + 3) % STAGES, kbase + (it + 3) * BKK);
        asm volatile("cp.async.commit_group;\n");
        asm volatile("cp.async.wait_group 3;\n");   // stage it%4 resident
        __syncthreads();

        const __nv_bfloat16* As = sh + (it % STAGES) * STAGE_H;
        const __nv_bfloat16* Bs = As + BM * S_LDH;

        #pragma unroll
        for (int ks = 0; ks < BKK / 16; ++ks) {
            wmma::fragment<wmma::matrix_a, 16, 16, 16, __nv_bfloat16, wmma::row_major> af[2];
            wmma::fragment<wmma::matrix_b, 16, 16, 16, __nv_bfloat16, wmma::col_major> bf[4];
            #pragma unroll
            for (int i = 0; i < 2; ++i)
                wmma::load_matrix_sync(af[i], As + (wm + i * 16) * S_LDH + ks * 16, S_LDH);
            #pragma unroll
            for (int j = 0; j < 4; ++j)
                wmma::load_matrix_sync(bf[j], Bs + (wn + j * 16) * S_LDH + ks * 16, S_LDH);
            #pragma unroll
            for (int i = 0; i < 2; ++i)
                #pragma unroll
                for (int j = 0; j < 4; ++j)
                    wmma::mma_sync(acc[i][j], af[i], bf[j], acc[i][j]);
        }
        __syncthreads();
    }

    float* base = g_part + (size_t)split * M_ * NPAD;
    #pragma unroll
    for (int i = 0; i < 2; ++i)
        #pragma unroll
        for (int j = 0; j < 4; ++j)
            wmma::store_matrix_sync(base + (size_t)(bm + wm + i * 16) * NPAD + (bn + wn + j * 16),
                                    acc[i][j], NPAD, wmma::mem_row_major);
}

// ---------------- kernel 3: fused split-K reduce + log-softmax NLL ----------------
__global__ __launch_bounds__(256) void nll_kernel(const float* __restrict__ bias,
                                                  const int* __restrict__ labels) {
    const int m = blockIdx.x;
    const int tid = threadIdx.x;
    const int lbl = labels[m];

    __shared__ float row[NPAD];   // 4 KB
    __shared__ float red[256];

    // reduce split-K partials + bias into smem (fixed order, deterministic)
    for (int c = tid; c < C_; c += 256) {
        float v = bias[c];
        #pragma unroll
        for (int s = 0; s < SPLITS; ++s)
            v += g_part[(size_t)s * M_ * NPAD + (size_t)m * NPAD + c];
        row[c] = v;
    }
    __syncthreads();

    float mx = -INFINITY;
    for (int c = tid; c < C_; c += 256) mx = fmaxf(mx, row[c]);
    red[tid] = mx;
    __syncthreads();
    for (int s = 128; s > 0; s >>= 1) {
        if (tid < s) red[tid] = fmaxf(red[tid], red[tid + s]);
        __syncthreads();
    }
    const float smax = red[0];
    __syncthreads();

    float sum = 0.0f;
    for (int c = tid; c < C_; c += 256) sum += __expf(row[c] - smax);
    red[tid] = sum;
    __syncthreads();
    for (int s = 128; s > 0; s >>= 1) {
        if (tid < s) red[tid] += red[tid + s];
        __syncthreads();
    }

    if (tid == 0) {
        if (lbl >= 0) {
            g_row_nll[m] = logf(red[0]) + smax - row[lbl];
            g_row_valid[m] = 1;
        } else {
            g_row_nll[m] = 0.0f;
            g_row_valid[m] = 0;
        }
    }
}

// ---------------- kernel 4: final reduction ----------------
__global__ __launch_bounds__(256) void finalize_kernel(float* __restrict__ out) {
    __shared__ float ssum[256];
    __shared__ int   scnt[256];
    const int tid = threadIdx.x;
    float s = 0.0f; int c = 0;
    for (int i = tid; i < M_; i += 256) { s += g_row_nll[i]; c += g_row_valid[i]; }
    ssum[tid] = s; scnt[tid] = c;
    __syncthreads();
    for (int st = 128; st > 0; st >>= 1) {
        if (tid < st) { ssum[tid] += ssum[tid + st]; scnt[tid] += scnt[tid + st]; }
        __syncthreads();
    }
    if (tid == 0) {
        int n = scnt[0] > 0 ? scnt[0] : 1;
        out[0] = ssum[0] / (float)n;
    }
}

// ---------------- launch ----------------
extern "C" void kernel_launch(void* const* d_in, const int* in_sizes, int n_in,
                              void* d_out, int out_size) {
    const float* feats  = (const float*)d_in[0];
    const float* Wmat   = (const float*)d_in[1];
    const float* bias   = (const float*)d_in[2];
    const int*   target = (const int*)d_in[4];
    const int*   lens   = (const int*)d_in[5];

    cudaFuncSetAttribute(gemm_kernel, cudaFuncAttributeMaxDynamicSharedMemorySize, SMEM_BYTES);

    pool_kernel<<<M_, 256>>>(feats, lens);
    convw_kernel<<<1184, 256>>>(Wmat);

    dim3 grid(NPAD / BN, M_ / BM, SPLITS);   // (8, 8, 4) = 256 CTAs
    gemm_kernel<<<grid, 256, SMEM_BYTES>>>();

    nll_kernel<<<M_, 256>>>(bias, target);
    finalize_kernel<<<1, 256>>>((float*)d_out);
}

// round 7
// speedup vs baseline: 6.2399x; 1.0474x over previous
#include <cuda_runtime.h>
#include <cuda_bf16.h>
#include <mma.h>
#include <math.h>
#include <cstdint>
#include <cstddef>

using namespace nvcuda;

// Problem constants
#define B_    16
#define NT_   64
#define T_    8
#define D_    25088
#define C_    1000
#define M_    (B_ * NT_)   // 1024
#define NPAD  1024
#define K_    D_

// GEMM tiling (bf16 WMMA)
#define BM     128
#define BN     128
#define BKK    64              // bf16 elements per K-chunk
#define STAGES 3
#define SPLITS 4
#define KSPLIT (K_ / SPLITS)   // 6272
#define NIT    (KSPLIT / BKK)  // 98
#define S_LDH  72              // padded smem row stride (bf16 elems) = 144B
#define STAGE_H ((BM + BN) * S_LDH)              // 18432 bf16
#define SMEM_BYTES (STAGES * STAGE_H * 2)        // 110592

// conv-W grid portion
#define CONVW_BLOCKS 1184

// ---------------- scratch ----------------
__device__ __nv_bfloat16 g_pooled_h[(size_t)M_ * K_];   // 51 MB
__device__ __nv_bfloat16 g_W_h[(size_t)C_ * K_];        // 50 MB
__device__ float g_part[(size_t)SPLITS * M_ * NPAD];    // 16 MB
__device__ float g_row_nll[M_];
__device__ int   g_row_valid[M_];

// ---------------- kernel 1: fused (pool -> bf16) + (W -> bf16) ----------------
__global__ __launch_bounds__(256) void prep_kernel(const float* __restrict__ feats,
                                                   const int* __restrict__ lens,
                                                   const float* __restrict__ W) {
    if (blockIdx.x < M_) {
        // pooling part
        const int m = blockIdx.x;
        const int b = m / NT_;
        const int len = lens[b];
        const float inv = 1.0f / (float)len;

        const float4* base = (const float4*)(feats + (size_t)m * T_ * D_);
        __nv_bfloat162* out = (__nv_bfloat162*)(g_pooled_h + (size_t)m * K_);
        const int nv = D_ / 4;

        for (int i = threadIdx.x; i < nv; i += blockDim.x) {
            float4 acc = make_float4(0.f, 0.f, 0.f, 0.f);
            #pragma unroll
            for (int t = 0; t < T_; ++t) {
                if (t < len) {
                    float4 v = base[(size_t)t * (D_ / 4) + i];
                    acc.x += v.x; acc.y += v.y; acc.z += v.z; acc.w += v.w;
                }
            }
            out[i * 2]     = __floats2bfloat162_rn(acc.x * inv, acc.y * inv);
            out[i * 2 + 1] = __floats2bfloat162_rn(acc.z * inv, acc.w * inv);
        }
    } else {
        // W conversion part
        const size_t n4 = (size_t)C_ * K_ / 4;
        const float4* src = (const float4*)W;
        __nv_bfloat162* dst = (__nv_bfloat162*)g_W_h;
        const size_t start = (size_t)(blockIdx.x - M_) * 256 + threadIdx.x;
        for (size_t i = start; i < n4; i += (size_t)CONVW_BLOCKS * 256) {
            float4 v = src[i];
            dst[i * 2]     = __floats2bfloat162_rn(v.x, v.y);
            dst[i * 2 + 1] = __floats2bfloat162_rn(v.z, v.w);
        }
    }
}

// ---------------- kernel 2: pipelined bf16 WMMA GEMM (split-K) ----------------
__device__ __forceinline__ void cp16(unsigned smem_dst, const void* gsrc, int src_sz) {
    asm volatile("cp.async.cg.shared.global [%0], [%1], 16, %2;\n"
                 :: "r"(smem_dst), "l"(gsrc), "r"(src_sz));
}

__global__ __launch_bounds__(256, 2) void gemm_kernel() {
    extern __shared__ __nv_bfloat16 sh[];

    const int bn    = blockIdx.x * BN;
    const int bm    = blockIdx.y * BM;
    const int split = blockIdx.z;
    const int kbase = split * KSPLIT;
    const int tid   = threadIdx.x;
    const int warp  = tid >> 5;
    const int wm    = (warp & 3) * 32;   // 4 warps along M
    const int wn    = (warp >> 2) * 64;  // 2 warps along N

    wmma::fragment<wmma::accumulator, 16, 16, 16, float> acc[2][4];
    #pragma unroll
    for (int i = 0; i < 2; ++i)
        #pragma unroll
        for (int j = 0; j < 4; ++j)
            wmma::fill_fragment(acc[i][j], 0.0f);

    // stage loader: A 128x64 bf16 + B 128x64 bf16; 16B = 8 elems, 8 chunks/row
    auto load_stage = [&](int stage, int k0) {
        __nv_bfloat16* As = sh + stage * STAGE_H;
        __nv_bfloat16* Bs = As + BM * S_LDH;
        #pragma unroll
        for (int i = 0; i < 4; ++i) {
            int idx = tid + i * 256;        // 0..1023
            int row = idx >> 3;
            int c   = (idx & 7) * 8;
            const __nv_bfloat16* src = g_pooled_h + (size_t)(bm + row) * K_ + k0 + c;
            unsigned dst = (unsigned)__cvta_generic_to_shared(As + row * S_LDH + c);
            cp16(dst, src, 16);
        }
        #pragma unroll
        for (int i = 0; i < 4; ++i) {
            int idx = tid + i * 256;
            int row = idx >> 3;
            int c   = (idx & 7) * 8;
            int brow = bn + row;
            int ok   = (brow < C_);
            const __nv_bfloat16* src = g_W_h + (size_t)(ok ? brow : 0) * K_ + k0 + c;
            unsigned dst = (unsigned)__cvta_generic_to_shared(Bs + row * S_LDH + c);
            cp16(dst, src, ok ? 16 : 0);   // zero-fill padded class rows
        }
    };

    load_stage(0, kbase);
    asm volatile("cp.async.commit_group;\n");
    load_stage(1, kbase + BKK);
    asm volatile("cp.async.commit_group;\n");

    for (int it = 0; it < NIT; ++it) {
        if (it + 2 < NIT)
            load_stage((it + 2) % STAGES, kbase + (it + 2) * BKK);
        asm volatile("cp.async.commit_group;\n");
        asm volatile("cp.async.wait_group 2;\n");   // stage it%3 resident
        __syncthreads();

        const __nv_bfloat16* As = sh + (it % STAGES) * STAGE_H;
        const __nv_bfloat16* Bs = As + BM * S_LDH;

        #pragma unroll
        for (int ks = 0; ks < BKK / 16; ++ks) {
            wmma::fragment<wmma::matrix_a, 16, 16, 16, __nv_bfloat16, wmma::row_major> af[2];
            wmma::fragment<wmma::matrix_b, 16, 16, 16, __nv_bfloat16, wmma::col_major> bf[4];
            #pragma unroll
            for (int i = 0; i < 2; ++i)
                wmma::load_matrix_sync(af[i], As + (wm + i * 16) * S_LDH + ks * 16, S_LDH);
            #pragma unroll
            for (int j = 0; j < 4; ++j)
                wmma::load_matrix_sync(bf[j], Bs + (wn + j * 16) * S_LDH + ks * 16, S_LDH);
            #pragma unroll
            for (int i = 0; i < 2; ++i)
                #pragma unroll
                for (int j = 0; j < 4; ++j)
                    wmma::mma_sync(acc[i][j], af[i], bf[j], acc[i][j]);
        }
        __syncthreads();   // stage consumed; safe to overwrite next iteration
    }

    float* base = g_part + (size_t)split * M_ * NPAD;
    #pragma unroll
    for (int i = 0; i < 2; ++i)
        #pragma unroll
        for (int j = 0; j < 4; ++j)
            wmma::store_matrix_sync(base + (size_t)(bm + wm + i * 16) * NPAD + (bn + wn + j * 16),
                                    acc[i][j], NPAD, wmma::mem_row_major);
}

// ---------------- kernel 3: fused split-K reduce + log-softmax NLL ----------------
__global__ __launch_bounds__(256) void nll_kernel(const float* __restrict__ bias,
                                                  const int* __restrict__ labels) {
    const int m = blockIdx.x;
    const int tid = threadIdx.x;
    const int lbl = labels[m];

    __shared__ float row[NPAD];
    __shared__ float red[256];

    for (int c = tid; c < C_; c += 256) {
        float v = bias[c];
        #pragma unroll
        for (int s = 0; s < SPLITS; ++s)
            v += g_part[(size_t)s * M_ * NPAD + (size_t)m * NPAD + c];
        row[c] = v;
    }
    __syncthreads();

    float mx = -INFINITY;
    for (int c = tid; c < C_; c += 256) mx = fmaxf(mx, row[c]);
    red[tid] = mx;
    __syncthreads();
    for (int s = 128; s > 0; s >>= 1) {
        if (tid < s) red[tid] = fmaxf(red[tid], red[tid + s]);
        __syncthreads();
    }
    const float smax = red[0];
    __syncthreads();

    float sum = 0.0f;
    for (int c = tid; c < C_; c += 256) sum += __expf(row[c] - smax);
    red[tid] = sum;
    __syncthreads();
    for (int s = 128; s > 0; s >>= 1) {
        if (tid < s) red[tid] += red[tid + s];
        __syncthreads();
    }

    if (tid == 0) {
        if (lbl >= 0) {
            g_row_nll[m] = logf(red[0]) + smax - row[lbl];
            g_row_valid[m] = 1;
        } else {
            g_row_nll[m] = 0.0f;
            g_row_valid[m] = 0;
        }
    }
}

// ---------------- kernel 4: final reduction ----------------
__global__ __launch_bounds__(256) void finalize_kernel(float* __restrict__ out) {
    __shared__ float ssum[256];
    __shared__ int   scnt[256];
    const int tid = threadIdx.x;
    float s = 0.0f; int c = 0;
    for (int i = tid; i < M_; i += 256) { s += g_row_nll[i]; c += g_row_valid[i]; }
    ssum[tid] = s; scnt[tid] = c;
    __syncthreads();
    for (int st = 128; st > 0; st >>= 1) {
        if (tid < st) { ssum[tid] += ssum[tid + st]; scnt[tid] += scnt[tid + st]; }
        __syncthreads();
    }
    if (tid == 0) {
        int n = scnt[0] > 0 ? scnt[0] : 1;
        out[0] = ssum[0] / (float)n;
    }
}

// ---------------- launch ----------------
extern "C" void kernel_launch(void* const* d_in, const int* in_sizes, int n_in,
                              void* d_out, int out_size) {
    const float* feats  = (const float*)d_in[0];
    const float* Wmat   = (const float*)d_in[1];
    const float* bias   = (const float*)d_in[2];
    const int*   target = (const int*)d_in[4];
    const int*   lens   = (const int*)d_in[5];

    cudaFuncSetAttribute(gemm_kernel, cudaFuncAttributeMaxDynamicSharedMemorySize, SMEM_BYTES);

    prep_kernel<<<M_ + CONVW_BLOCKS, 256>>>(feats, lens, Wmat);

    dim3 grid(NPAD / BN, M_ / BM, SPLITS);   // (8, 8, 4) = 256 CTAs
    gemm_kernel<<<grid, 256, SMEM_BYTES>>>();

    nll_kernel<<<M_, 256>>>(bias, target);
    finalize_kernel<<<1, 256>>>((float*)d_out);
}

// round 8
// speedup vs baseline: 6.4432x; 1.0326x over previous
#include <cuda_runtime.h>
#include <cuda_bf16.h>
#include <mma.h>
#include <math.h>
#include <cstdint>
#include <cstddef>

using namespace nvcuda;

// Problem constants
#define B_    16
#define NT_   64
#define T_    8
#define D_    25088
#define C_    1000
#define M_    (B_ * NT_)   // 1024
#define NPAD  1024
#define K_    D_

// GEMM tiling (bf16 WMMA, 64x64 warp tiles)
#define BM     128
#define BN     128
#define BKK    64              // bf16 elements per K-chunk
#define STAGES 3
#define SPLITS 4
#define KSPLIT (K_ / SPLITS)   // 6272
#define NIT    (KSPLIT / BKK)  // 98
#define S_LDH  72              // padded smem row stride (bf16 elems) = 144B
#define STAGE_H ((BM + BN) * S_LDH)              // 18432 bf16
#define SMEM_BYTES (STAGES * STAGE_H * 2)        // 110592

#define CONVW_BLOCKS 1184

// ---------------- scratch ----------------
__device__ __nv_bfloat16 g_pooled_h[(size_t)M_ * K_];   // 51 MB
__device__ __nv_bfloat16 g_W_h[(size_t)C_ * K_];        // 50 MB
__device__ float g_part[(size_t)SPLITS * M_ * NPAD];    // 16 MB
__device__ float g_row_nll[M_];
__device__ int   g_row_valid[M_];

// ---------------- kernel 1: fused (pool -> bf16) + (W -> bf16) ----------------
__global__ __launch_bounds__(256) void prep_kernel(const float* __restrict__ feats,
                                                   const int* __restrict__ lens,
                                                   const float* __restrict__ W) {
    if (blockIdx.x < M_) {
        const int m = blockIdx.x;
        const int b = m / NT_;
        const int len = lens[b];
        const float inv = 1.0f / (float)len;

        const float4* base = (const float4*)(feats + (size_t)m * T_ * D_);
        __nv_bfloat162* out = (__nv_bfloat162*)(g_pooled_h + (size_t)m * K_);
        const int nv = D_ / 4;

        for (int i = threadIdx.x; i < nv; i += blockDim.x) {
            float4 acc = make_float4(0.f, 0.f, 0.f, 0.f);
            #pragma unroll
            for (int t = 0; t < T_; ++t) {
                if (t < len) {
                    float4 v = base[(size_t)t * (D_ / 4) + i];
                    acc.x += v.x; acc.y += v.y; acc.z += v.z; acc.w += v.w;
                }
            }
            out[i * 2]     = __floats2bfloat162_rn(acc.x * inv, acc.y * inv);
            out[i * 2 + 1] = __floats2bfloat162_rn(acc.z * inv, acc.w * inv);
        }
    } else {
        const size_t n4 = (size_t)C_ * K_ / 4;
        const float4* src = (const float4*)W;
        __nv_bfloat162* dst = (__nv_bfloat162*)g_W_h;
        const size_t start = (size_t)(blockIdx.x - M_) * 256 + threadIdx.x;
        for (size_t i = start; i < n4; i += (size_t)CONVW_BLOCKS * 256) {
            float4 v = src[i];
            dst[i * 2]     = __floats2bfloat162_rn(v.x, v.y);
            dst[i * 2 + 1] = __floats2bfloat162_rn(v.z, v.w);
        }
    }
}

// ---------------- kernel 2: pipelined bf16 WMMA GEMM, 64x64 warp tiles -------
__device__ __forceinline__ void cp16(unsigned smem_dst, const void* gsrc, int src_sz) {
    asm volatile("cp.async.cg.shared.global [%0], [%1], 16, %2;\n"
                 :: "r"(smem_dst), "l"(gsrc), "r"(src_sz));
}

__global__ __launch_bounds__(128, 2) void gemm_kernel() {
    extern __shared__ __nv_bfloat16 sh[];

    const int bn    = blockIdx.x * BN;
    const int bm    = blockIdx.y * BM;
    const int split = blockIdx.z;
    const int kbase = split * KSPLIT;
    const int tid   = threadIdx.x;       // 128 threads
    const int warp  = tid >> 5;          // 0..3
    const int wm    = (warp & 1) * 64;   // 2 warps along M
    const int wn    = (warp >> 1) * 64;  // 2 warps along N

    wmma::fragment<wmma::accumulator, 16, 16, 16, float> acc[4][4];
    #pragma unroll
    for (int i = 0; i < 4; ++i)
        #pragma unroll
        for (int j = 0; j < 4; ++j)
            wmma::fill_fragment(acc[i][j], 0.0f);

    // stage loader: A 128x64 + B 128x64 bf16, 16B chunks; 2048 chunks, 128 thr -> 16 each
    auto load_stage = [&](int stage, int k0) {
        __nv_bfloat16* As = sh + stage * STAGE_H;
        __nv_bfloat16* Bs = As + BM * S_LDH;
        #pragma unroll
        for (int i = 0; i < 8; ++i) {
            int idx = tid + i * 128;        // 0..1023
            int row = idx >> 3;
            int c   = (idx & 7) * 8;
            const __nv_bfloat16* src = g_pooled_h + (size_t)(bm + row) * K_ + k0 + c;
            unsigned dst = (unsigned)__cvta_generic_to_shared(As + row * S_LDH + c);
            cp16(dst, src, 16);
        }
        #pragma unroll
        for (int i = 0; i < 8; ++i) {
            int idx = tid + i * 128;
            int row = idx >> 3;
            int c   = (idx & 7) * 8;
            int brow = bn + row;
            int ok   = (brow < C_);
            const __nv_bfloat16* src = g_W_h + (size_t)(ok ? brow : 0) * K_ + k0 + c;
            unsigned dst = (unsigned)__cvta_generic_to_shared(Bs + row * S_LDH + c);
            cp16(dst, src, ok ? 16 : 0);
        }
    };

    load_stage(0, kbase);
    asm volatile("cp.async.commit_group;\n");
    load_stage(1, kbase + BKK);
    asm volatile("cp.async.commit_group;\n");

    for (int it = 0; it < NIT; ++it) {
        if (it + 2 < NIT)
            load_stage((it + 2) % STAGES, kbase + (it + 2) * BKK);
        asm volatile("cp.async.commit_group;\n");
        asm volatile("cp.async.wait_group 2;\n");
        __syncthreads();

        const __nv_bfloat16* As = sh + (it % STAGES) * STAGE_H;
        const __nv_bfloat16* Bs = As + BM * S_LDH;

        #pragma unroll
        for (int ks = 0; ks < BKK / 16; ++ks) {
            wmma::fragment<wmma::matrix_a, 16, 16, 16, __nv_bfloat16, wmma::row_major> af[4];
            wmma::fragment<wmma::matrix_b, 16, 16, 16, __nv_bfloat16, wmma::col_major> bf[4];
            #pragma unroll
            for (int i = 0; i < 4; ++i)
                wmma::load_matrix_sync(af[i], As + (wm + i * 16) * S_LDH + ks * 16, S_LDH);
            #pragma unroll
            for (int j = 0; j < 4; ++j)
                wmma::load_matrix_sync(bf[j], Bs + (wn + j * 16) * S_LDH + ks * 16, S_LDH);
            #pragma unroll
            for (int i = 0; i < 4; ++i)
                #pragma unroll
                for (int j = 0; j < 4; ++j)
                    wmma::mma_sync(acc[i][j], af[i], bf[j], acc[i][j]);
        }
        __syncthreads();
    }

    float* base = g_part + (size_t)split * M_ * NPAD;
    #pragma unroll
    for (int i = 0; i < 4; ++i)
        #pragma unroll
        for (int j = 0; j < 4; ++j)
            wmma::store_matrix_sync(base + (size_t)(bm + wm + i * 16) * NPAD + (bn + wn + j * 16),
                                    acc[i][j], NPAD, wmma::mem_row_major);
}

// ---------------- kernel 3: fused split-K reduce + log-softmax NLL ----------------
__global__ __launch_bounds__(256) void nll_kernel(const float* __restrict__ bias,
                                                  const int* __restrict__ labels) {
    const int m = blockIdx.x;
    const int tid = threadIdx.x;
    const int lbl = labels[m];

    __shared__ float row[NPAD];
    __shared__ float red[256];

    for (int c = tid; c < C_; c += 256) {
        float v = bias[c];
        #pragma unroll
        for (int s = 0; s < SPLITS; ++s)
            v += g_part[(size_t)s * M_ * NPAD + (size_t)m * NPAD + c];
        row[c] = v;
    }
    __syncthreads();

    float mx = -INFINITY;
    for (int c = tid; c < C_; c += 256) mx = fmaxf(mx, row[c]);
    red[tid] = mx;
    __syncthreads();
    for (int s = 128; s > 0; s >>= 1) {
        if (tid < s) red[tid] = fmaxf(red[tid], red[tid + s]);
        __syncthreads();
    }
    const float smax = red[0];
    __syncthreads();

    float sum = 0.0f;
    for (int c = tid; c < C_; c += 256) sum += __expf(row[c] - smax);
    red[tid] = sum;
    __syncthreads();
    for (int s = 128; s > 0; s >>= 1) {
        if (tid < s) red[tid] += red[tid + s];
        __syncthreads();
    }

    if (tid == 0) {
        if (lbl >= 0) {
            g_row_nll[m] = logf(red[0]) + smax - row[lbl];
            g_row_valid[m] = 1;
        } else {
            g_row_nll[m] = 0.0f;
            g_row_valid[m] = 0;
        }
    }
}

// ---------------- kernel 4: final reduction ----------------
__global__ __launch_bounds__(256) void finalize_kernel(float* __restrict__ out) {
    __shared__ float ssum[256];
    __shared__ int   scnt[256];
    const int tid = threadIdx.x;
    float s = 0.0f; int c = 0;
    for (int i = tid; i < M_; i += 256) { s += g_row_nll[i]; c += g_row_valid[i]; }
    ssum[tid] = s; scnt[tid] = c;
    __syncthreads();
    for (int st = 128; st > 0; st >>= 1) {
        if (tid < st) { ssum[tid] += ssum[tid + st]; scnt[tid] += scnt[tid + st]; }
        __syncthreads();
    }
    if (tid == 0) {
        int n = scnt[0] > 0 ? scnt[0] : 1;
        out[0] = ssum[0] / (float)n;
    }
}

// ---------------- launch ----------------
extern "C" void kernel_launch(void* const* d_in, const int* in_sizes, int n_in,
                              void* d_out, int out_size) {
    const float* feats  = (const float*)d_in[0];
    const float* Wmat   = (const float*)d_in[1];
    const float* bias   = (const float*)d_in[2];
    const int*   target = (const int*)d_in[4];
    const int*   lens   = (const int*)d_in[5];

    cudaFuncSetAttribute(gemm_kernel, cudaFuncAttributeMaxDynamicSharedMemorySize, SMEM_BYTES);

    prep_kernel<<<M_ + CONVW_BLOCKS, 256>>>(feats, lens, Wmat);

    dim3 grid(NPAD / BN, M_ / BM, SPLITS);   // (8, 8, 4) = 256 CTAs
    gemm_kernel<<<grid, 128, SMEM_BYTES>>>();

    nll_kernel<<<M_, 256>>>(bias, target);
    finalize_kernel<<<1, 256>>>((float*)d_out);
}

// round 9
// speedup vs baseline: 6.6376x; 1.0302x over previous
#include <cuda_runtime.h>
#include <cuda_bf16.h>
#include <cuda_fp8.h>
#include <math.h>
#include <cstdint>
#include <cstddef>

// Problem constants
#define B_    16
#define NT_   64
#define T_    8
#define D_    25088
#define C_    1000
#define M_    (B_ * NT_)   // 1024
#define NPAD  1024
#define K_    D_

// FP8 scaling
#define SCALE_A  64.0f
#define SCALE_W  2048.0f
#define INV_SCALE (1.0f / (SCALE_A * SCALE_W))   // 1/131072

// GEMM tiling (fp8 mma.sync m16n8k32)
#define BM     128
#define BN     128
#define BKK    128             // fp8 elements per K-chunk (128 bytes/row)
#define STAGES 3
#define SPLITS 4
#define KSPLIT (K_ / SPLITS)   // 6272
#define NIT    (KSPLIT / BKK)  // 49
#define S_LDB  144             // padded smem row stride in bytes
#define STAGE_BYTES ((BM + BN) * S_LDB)          // 36864
#define SMEM_BYTES  (STAGES * STAGE_BYTES)       // 110592

#define CONVW_BLOCKS 1184

// ---------------- scratch ----------------
__device__ uint8_t g_pooled_8[(size_t)M_ * K_];        // 25.7 MB (e4m3)
__device__ uint8_t g_W_8[(size_t)C_ * K_];             // 25 MB   (e4m3)
__device__ float g_part[(size_t)SPLITS * M_ * NPAD];   // 16 MB
__device__ float g_row_nll[M_];
__device__ int   g_row_valid[M_];

__device__ __forceinline__ uint8_t to_e4m3(float v) {
    return (uint8_t)__nv_cvt_float_to_fp8(v, __NV_SATFINITE, __NV_E4M3);
}

// ---------------- kernel 1: fused (pool -> fp8) + (W -> fp8) ----------------
__global__ __launch_bounds__(256) void prep_kernel(const float* __restrict__ feats,
                                                   const int* __restrict__ lens,
                                                   const float* __restrict__ W) {
    if (blockIdx.x < M_) {
        const int m = blockIdx.x;
        const int b = m / NT_;
        const int len = lens[b];
        const float inv = SCALE_A / (float)len;

        const float4* base = (const float4*)(feats + (size_t)m * T_ * D_);
        uchar4* out = (uchar4*)(g_pooled_8 + (size_t)m * K_);
        const int nv = D_ / 4;

        for (int i = threadIdx.x; i < nv; i += blockDim.x) {
            float4 acc = make_float4(0.f, 0.f, 0.f, 0.f);
            #pragma unroll
            for (int t = 0; t < T_; ++t) {
                if (t < len) {
                    float4 v = base[(size_t)t * (D_ / 4) + i];
                    acc.x += v.x; acc.y += v.y; acc.z += v.z; acc.w += v.w;
                }
            }
            uchar4 o;
            o.x = to_e4m3(acc.x * inv);
            o.y = to_e4m3(acc.y * inv);
            o.z = to_e4m3(acc.z * inv);
            o.w = to_e4m3(acc.w * inv);
            out[i] = o;
        }
    } else {
        const size_t n4 = (size_t)C_ * K_ / 4;
        const float4* src = (const float4*)W;
        uchar4* dst = (uchar4*)g_W_8;
        const size_t start = (size_t)(blockIdx.x - M_) * 256 + threadIdx.x;
        for (size_t i = start; i < n4; i += (size_t)CONVW_BLOCKS * 256) {
            float4 v = src[i];
            uchar4 o;
            o.x = to_e4m3(v.x * SCALE_W);
            o.y = to_e4m3(v.y * SCALE_W);
            o.z = to_e4m3(v.z * SCALE_W);
            o.w = to_e4m3(v.w * SCALE_W);
            dst[i] = o;
        }
    }
}

// ---------------- kernel 2: pipelined fp8 mma GEMM (split-K) ----------------
__device__ __forceinline__ void cp16(unsigned smem_dst, const void* gsrc, int src_sz) {
    asm volatile("cp.async.cg.shared.global [%0], [%1], 16, %2;\n"
                 :: "r"(smem_dst), "l"(gsrc), "r"(src_sz));
}

__device__ __forceinline__ void mma_e4m3(float* d, const uint32_t* a, const uint32_t* b) {
    asm volatile(
        "mma.sync.aligned.m16n8k32.row.col.f32.e4m3.e4m3.f32 "
        "{%0,%1,%2,%3}, {%4,%5,%6,%7}, {%8,%9}, {%0,%1,%2,%3};"
        : "+f"(d[0]), "+f"(d[1]), "+f"(d[2]), "+f"(d[3])
        : "r"(a[0]), "r"(a[1]), "r"(a[2]), "r"(a[3]), "r"(b[0]), "r"(b[1]));
}

__global__ __launch_bounds__(256, 2) void gemm_kernel() {
    extern __shared__ uint8_t sh[];

    const int bn    = blockIdx.x * BN;
    const int bm    = blockIdx.y * BM;
    const int split = blockIdx.z;
    const int kbase = split * KSPLIT;
    const int tid   = threadIdx.x;       // 256 threads, 8 warps
    const int warp  = tid >> 5;
    const int lane  = tid & 31;
    const int q     = lane >> 2;         // groupID 0..7
    const int r4    = (lane & 3) * 4;    // k-byte offset within fragment
    const int wm    = (warp & 3) * 32;   // 4 warps along M (32 rows each)
    const int wn    = (warp >> 2) * 64;  // 2 warps along N (64 cols each)

    float acc[2][8][4];
    #pragma unroll
    for (int i = 0; i < 2; ++i)
        #pragma unroll
        for (int j = 0; j < 8; ++j)
            #pragma unroll
            for (int e = 0; e < 4; ++e)
                acc[i][j][e] = 0.0f;

    // stage loader: A 128x128B + B 128x128B; 16B chunks; 2048 chunks / 256 thr = 8 each
    auto load_stage = [&](int stage, int k0) {
        uint8_t* As = sh + stage * STAGE_BYTES;
        uint8_t* Bs = As + BM * S_LDB;
        #pragma unroll
        for (int i = 0; i < 4; ++i) {
            int idx = tid + i * 256;        // 0..1023
            int row = idx >> 3;
            int c   = (idx & 7) * 16;
            const uint8_t* src = g_pooled_8 + (size_t)(bm + row) * K_ + k0 + c;
            unsigned dst = (unsigned)__cvta_generic_to_shared(As + row * S_LDB + c);
            cp16(dst, src, 16);
        }
        #pragma unroll
        for (int i = 0; i < 4; ++i) {
            int idx = tid + i * 256;
            int row = idx >> 3;
            int c   = (idx & 7) * 16;
            int brow = bn + row;
            int ok   = (brow < C_);
            const uint8_t* src = g_W_8 + (size_t)(ok ? brow : 0) * K_ + k0 + c;
            unsigned dst = (unsigned)__cvta_generic_to_shared(Bs + row * S_LDB + c);
            cp16(dst, src, ok ? 16 : 0);   // zero-fill padded class rows
        }
    };

    load_stage(0, kbase);
    asm volatile("cp.async.commit_group;\n");
    load_stage(1, kbase + BKK);
    asm volatile("cp.async.commit_group;\n");

    for (int it = 0; it < NIT; ++it) {
        if (it + 2 < NIT)
            load_stage((it + 2) % STAGES, kbase + (it + 2) * BKK);
        asm volatile("cp.async.commit_group;\n");
        asm volatile("cp.async.wait_group 2;\n");
        __syncthreads();

        const uint8_t* As = sh + (it % STAGES) * STAGE_BYTES;
        const uint8_t* Bs = As + BM * S_LDB;

        #pragma unroll
        for (int ks = 0; ks < BKK / 32; ++ks) {      // 4 k32 steps
            const int kb = ks * 32 + r4;
            uint32_t a[2][4], b[8][2];
            #pragma unroll
            for (int i = 0; i < 2; ++i) {
                const uint8_t* base0 = As + (wm + i * 16 + q) * S_LDB + kb;
                const uint8_t* base1 = base0 + 8 * S_LDB;
                a[i][0] = *(const uint32_t*)(base0);
                a[i][1] = *(const uint32_t*)(base1);
                a[i][2] = *(const uint32_t*)(base0 + 16);
                a[i][3] = *(const uint32_t*)(base1 + 16);
            }
            #pragma unroll
            for (int j = 0; j < 8; ++j) {
                const uint8_t* nb = Bs + (wn + j * 8 + q) * S_LDB + kb;
                b[j][0] = *(const uint32_t*)(nb);
                b[j][1] = *(const uint32_t*)(nb + 16);
            }
            #pragma unroll
            for (int i = 0; i < 2; ++i)
                #pragma unroll
                for (int j = 0; j < 8; ++j)
                    mma_e4m3(acc[i][j], a[i], b[j]);
        }
        __syncthreads();
    }

    // epilogue
    float* base = g_part + (size_t)split * M_ * NPAD;
    #pragma unroll
    for (int i = 0; i < 2; ++i) {
        const int row0 = bm + wm + i * 16 + q;
        #pragma unroll
        for (int j = 0; j < 8; ++j) {
            const int col = bn + wn + j * 8 + (lane & 3) * 2;
            float2 v0 = make_float2(acc[i][j][0], acc[i][j][1]);
            float2 v1 = make_float2(acc[i][j][2], acc[i][j][3]);
            *(float2*)(base + (size_t)row0 * NPAD + col) = v0;
            *(float2*)(base + (size_t)(row0 + 8) * NPAD + col) = v1;
        }
    }
}

// ---------------- kernel 3: fused split-K reduce + dequant + log-softmax NLL ----
__global__ __launch_bounds__(256) void nll_kernel(const float* __restrict__ bias,
                                                  const int* __restrict__ labels) {
    const int m = blockIdx.x;
    const int tid = threadIdx.x;
    const int lbl = labels[m];

    __shared__ float row[NPAD];
    __shared__ float red[256];

    for (int c = tid; c < C_; c += 256) {
        float v = 0.0f;
        #pragma unroll
        for (int s = 0; s < SPLITS; ++s)
            v += g_part[(size_t)s * M_ * NPAD + (size_t)m * NPAD + c];
        row[c] = v * INV_SCALE + bias[c];
    }
    __syncthreads();

    float mx = -INFINITY;
    for (int c = tid; c < C_; c += 256) mx = fmaxf(mx, row[c]);
    red[tid] = mx;
    __syncthreads();
    for (int s = 128; s > 0; s >>= 1) {
        if (tid < s) red[tid] = fmaxf(red[tid], red[tid + s]);
        __syncthreads();
    }
    const float smax = red[0];
    __syncthreads();

    float sum = 0.0f;
    for (int c = tid; c < C_; c += 256) sum += __expf(row[c] - smax);
    red[tid] = sum;
    __syncthreads();
    for (int s = 128; s > 0; s >>= 1) {
        if (tid < s) red[tid] += red[tid + s];
        __syncthreads();
    }

    if (tid == 0) {
        if (lbl >= 0) {
            g_row_nll[m] = logf(red[0]) + smax - row[lbl];
            g_row_valid[m] = 1;
        } else {
            g_row_nll[m] = 0.0f;
            g_row_valid[m] = 0;
        }
    }
}

// ---------------- kernel 4: final reduction ----------------
__global__ __launch_bounds__(256) void finalize_kernel(float* __restrict__ out) {
    __shared__ float ssum[256];
    __shared__ int   scnt[256];
    const int tid = threadIdx.x;
    float s = 0.0f; int c = 0;
    for (int i = tid; i < M_; i += 256) { s += g_row_nll[i]; c += g_row_valid[i]; }
    ssum[tid] = s; scnt[tid] = c;
    __syncthreads();
    for (int st = 128; st > 0; st >>= 1) {
        if (tid < st) { ssum[tid] += ssum[tid + st]; scnt[tid] += scnt[tid + st]; }
        __syncthreads();
    }
    if (tid == 0) {
        int n = scnt[0] > 0 ? scnt[0] : 1;
        out[0] = ssum[0] / (float)n;
    }
}

// ---------------- launch ----------------
extern "C" void kernel_launch(void* const* d_in, const int* in_sizes, int n_in,
                              void* d_out, int out_size) {
    const float* feats  = (const float*)d_in[0];
    const float* Wmat   = (const float*)d_in[1];
    const float* bias   = (const float*)d_in[2];
    const int*   target = (const int*)d_in[4];
    const int*   lens   = (const int*)d_in[5];

    cudaFuncSetAttribute(gemm_kernel, cudaFuncAttributeMaxDynamicSharedMemorySize, SMEM_BYTES);

    prep_kernel<<<M_ + CONVW_BLOCKS, 256>>>(feats, lens, Wmat);

    dim3 grid(NPAD / BN, M_ / BM, SPLITS);   // (8, 8, 4) = 256 CTAs
    gemm_kernel<<<grid, 256, SMEM_BYTES>>>();

    nll_kernel<<<M_, 256>>>(bias, target);
    finalize_kernel<<<1, 256>>>((float*)d_out);
}

// round 10
// speedup vs baseline: 6.6682x; 1.0046x over previous
#include <cuda_runtime.h>
#include <cuda_bf16.h>
#include <cuda_fp8.h>
#include <math.h>
#include <cstdint>
#include <cstddef>

// Problem constants
#define B_    16
#define NT_   64
#define T_    8
#define D_    25088
#define C_    1000
#define M_    (B_ * NT_)   // 1024
#define NPAD  1024
#define K_    D_

// FP8 scaling
#define SCALE_A  64.0f
#define SCALE_W  2048.0f
#define INV_SCALE (1.0f / (SCALE_A * SCALE_W))   // 1/131072

// GEMM tiling (fp8 mma.sync m16n8k32)
#define BM     128
#define BN     128
#define BKK    128             // fp8 elements per K-chunk (128 bytes/row)
#define STAGES 3
#define SPLITS 4
#define KSPLIT (K_ / SPLITS)   // 6272
#define NIT    (KSPLIT / BKK)  // 49
#define S_LDB  144             // padded smem row stride in bytes
#define STAGE_BYTES ((BM + BN) * S_LDB)          // 36864
#define SMEM_BYTES  (STAGES * STAGE_BYTES)       // 110592

#define CONVW_BLOCKS 1184

// ---------------- scratch ----------------
__device__ uint8_t g_pooled_8[(size_t)M_ * K_];        // 25.7 MB (e4m3)
__device__ uint8_t g_W_8[(size_t)C_ * K_];             // 25 MB   (e4m3)
__device__ float g_part[(size_t)SPLITS * M_ * NPAD];   // 16 MB
__device__ float g_row_nll[M_];
__device__ int   g_row_valid[M_];

__device__ __forceinline__ uint8_t to_e4m3(float v) {
    return (uint8_t)__nv_cvt_float_to_fp8(v, __NV_SATFINITE, __NV_E4M3);
}

// ---------------- kernel 1: fused (pool -> fp8) + (W -> fp8) ----------------
__global__ __launch_bounds__(256) void prep_kernel(const float* __restrict__ feats,
                                                   const int* __restrict__ lens,
                                                   const float* __restrict__ W) {
    if (blockIdx.x < M_) {
        const int m = blockIdx.x;
        const int b = m / NT_;
        const int len = lens[b];
        const float inv = SCALE_A / (float)len;

        const float4* base = (const float4*)(feats + (size_t)m * T_ * D_);
        uchar4* out = (uchar4*)(g_pooled_8 + (size_t)m * K_);
        const int nv = D_ / 4;

        for (int i = threadIdx.x; i < nv; i += blockDim.x) {
            float4 acc = make_float4(0.f, 0.f, 0.f, 0.f);
            #pragma unroll
            for (int t = 0; t < T_; ++t) {
                if (t < len) {
                    float4 v = base[(size_t)t * (D_ / 4) + i];
                    acc.x += v.x; acc.y += v.y; acc.z += v.z; acc.w += v.w;
                }
            }
            uchar4 o;
            o.x = to_e4m3(acc.x * inv);
            o.y = to_e4m3(acc.y * inv);
            o.z = to_e4m3(acc.z * inv);
            o.w = to_e4m3(acc.w * inv);
            out[i] = o;
        }
    } else {
        const size_t n4 = (size_t)C_ * K_ / 4;
        const float4* src = (const float4*)W;
        uchar4* dst = (uchar4*)g_W_8;
        const size_t start = (size_t)(blockIdx.x - M_) * 256 + threadIdx.x;
        for (size_t i = start; i < n4; i += (size_t)CONVW_BLOCKS * 256) {
            float4 v = src[i];
            uchar4 o;
            o.x = to_e4m3(v.x * SCALE_W);
            o.y = to_e4m3(v.y * SCALE_W);
            o.z = to_e4m3(v.z * SCALE_W);
            o.w = to_e4m3(v.w * SCALE_W);
            dst[i] = o;
        }
    }
}

// ---------------- kernel 2: pipelined fp8 mma GEMM (split-K) ----------------
__device__ __forceinline__ void cp16(unsigned smem_dst, const void* gsrc, int src_sz) {
    asm volatile("cp.async.cg.shared.global [%0], [%1], 16, %2;\n"
                 :: "r"(smem_dst), "l"(gsrc), "r"(src_sz));
}

__device__ __forceinline__ void mma_e4m3(float* d, const uint32_t* a, const uint32_t* b) {
    asm volatile(
        "mma.sync.aligned.m16n8k32.row.col.f32.e4m3.e4m3.f32 "
        "{%0,%1,%2,%3}, {%4,%5,%6,%7}, {%8,%9}, {%0,%1,%2,%3};"
        : "+f"(d[0]), "+f"(d[1]), "+f"(d[2]), "+f"(d[3])
        : "r"(a[0]), "r"(a[1]), "r"(a[2]), "r"(a[3]), "r"(b[0]), "r"(b[1]));
}

__global__ __launch_bounds__(256, 2) void gemm_kernel() {
    extern __shared__ uint8_t sh[];

    const int bn    = blockIdx.x * BN;
    const int bm    = blockIdx.y * BM;
    const int split = blockIdx.z;
    const int kbase = split * KSPLIT;
    const int tid   = threadIdx.x;       // 256 threads, 8 warps
    const int warp  = tid >> 5;
    const int lane  = tid & 31;
    const int q     = lane >> 2;         // groupID 0..7
    const int r4    = (lane & 3) * 4;    // k-byte offset within fragment
    const int wm    = (warp & 3) * 32;   // 4 warps along M (32 rows each)
    const int wn    = (warp >> 2) * 64;  // 2 warps along N (64 cols each)

    float acc[2][8][4];
    #pragma unroll
    for (int i = 0; i < 2; ++i)
        #pragma unroll
        for (int j = 0; j < 8; ++j)
            #pragma unroll
            for (int e = 0; e < 4; ++e)
                acc[i][j][e] = 0.0f;

    // stage loader: A 128x128B + B 128x128B; 16B chunks; 2048 chunks / 256 thr = 8 each
    auto load_stage = [&](int stage, int k0) {
        uint8_t* As = sh + stage * STAGE_BYTES;
        uint8_t* Bs = As + BM * S_LDB;
        #pragma unroll
        for (int i = 0; i < 4; ++i) {
            int idx = tid + i * 256;        // 0..1023
            int row = idx >> 3;
            int c   = (idx & 7) * 16;
            const uint8_t* src = g_pooled_8 + (size_t)(bm + row) * K_ + k0 + c;
            unsigned dst = (unsigned)__cvta_generic_to_shared(As + row * S_LDB + c);
            cp16(dst, src, 16);
        }
        #pragma unroll
        for (int i = 0; i < 4; ++i) {
            int idx = tid + i * 256;
            int row = idx >> 3;
            int c   = (idx & 7) * 16;
            int brow = bn + row;
            int ok   = (brow < C_);
            const uint8_t* src = g_W_8 + (size_t)(ok ? brow : 0) * K_ + k0 + c;
            unsigned dst = (unsigned)__cvta_generic_to_shared(Bs + row * S_LDB + c);
            cp16(dst, src, ok ? 16 : 0);   // zero-fill padded class rows
        }
    };

    load_stage(0, kbase);
    asm volatile("cp.async.commit_group;\n");
    load_stage(1, kbase + BKK);
    asm volatile("cp.async.commit_group;\n");

    for (int it = 0; it < NIT; ++it) {
        if (it + 2 < NIT)
            load_stage((it + 2) % STAGES, kbase + (it + 2) * BKK);
        asm volatile("cp.async.commit_group;\n");
        asm volatile("cp.async.wait_group 2;\n");
        __syncthreads();

        const uint8_t* As = sh + (it % STAGES) * STAGE_BYTES;
        const uint8_t* Bs = As + BM * S_LDB;

        #pragma unroll
        for (int ks = 0; ks < BKK / 32; ++ks) {      // 4 k32 steps
            const int kb = ks * 32 + r4;
            uint32_t a[2][4], b[8][2];
            #pragma unroll
            for (int i = 0; i < 2; ++i) {
                const uint8_t* base0 = As + (wm + i * 16 + q) * S_LDB + kb;
                const uint8_t* base1 = base0 + 8 * S_LDB;
                a[i][0] = *(const uint32_t*)(base0);
                a[i][1] = *(const uint32_t*)(base1);
                a[i][2] = *(const uint32_t*)(base0 + 16);
                a[i][3] = *(const uint32_t*)(base1 + 16);
            }
            #pragma unroll
            for (int j = 0; j < 8; ++j) {
                const uint8_t* nb = Bs + (wn + j * 8 + q) * S_LDB + kb;
                b[j][0] = *(const uint32_t*)(nb);
                b[j][1] = *(const uint32_t*)(nb + 16);
            }
            #pragma unroll
            for (int i = 0; i < 2; ++i)
                #pragma unroll
                for (int j = 0; j < 8; ++j)
                    mma_e4m3(acc[i][j], a[i], b[j]);
        }
        __syncthreads();
    }

    // epilogue
    float* base = g_part + (size_t)split * M_ * NPAD;
    #pragma unroll
    for (int i = 0; i < 2; ++i) {
        const int row0 = bm + wm + i * 16 + q;
        #pragma unroll
        for (int j = 0; j < 8; ++j) {
            const int col = bn + wn + j * 8 + (lane & 3) * 2;
            float2 v0 = make_float2(acc[i][j][0], acc[i][j][1]);
            float2 v1 = make_float2(acc[i][j][2], acc[i][j][3]);
            *(float2*)(base + (size_t)row0 * NPAD + col) = v0;
            *(float2*)(base + (size_t)(row0 + 8) * NPAD + col) = v1;
        }
    }
}

// ---------------- kernel 3: fused split-K reduce + dequant + log-softmax NLL ----
__global__ __launch_bounds__(256) void nll_kernel(const float* __restrict__ bias,
                                                  const int* __restrict__ labels) {
    const int m = blockIdx.x;
    const int tid = threadIdx.x;
    const int lbl = labels[m];

    __shared__ float row[NPAD];
    __shared__ float red[256];

    for (int c = tid; c < C_; c += 256) {
        float v = 0.0f;
        #pragma unroll
        for (int s = 0; s < SPLITS; ++s)
            v += g_part[(size_t)s * M_ * NPAD + (size_t)m * NPAD + c];
        row[c] = v * INV_SCALE + bias[c];
    }
    __syncthreads();

    float mx = -INFINITY;
    for (int c = tid; c < C_; c += 256) mx = fmaxf(mx, row[c]);
    red[tid] = mx;
    __syncthreads();
    for (int s = 128; s > 0; s >>= 1) {
        if (tid < s) red[tid] = fmaxf(red[tid], red[tid + s]);
        __syncthreads();
    }
    const float smax = red[0];
    __syncthreads();

    float sum = 0.0f;
    for (int c = tid; c < C_; c += 256) sum += __expf(row[c] - smax);
    red[tid] = sum;
    __syncthreads();
    for (int s = 128; s > 0; s >>= 1) {
        if (tid < s) red[tid] += red[tid + s];
        __syncthreads();
    }

    if (tid == 0) {
        if (lbl >= 0) {
            g_row_nll[m] = logf(red[0]) + smax - row[lbl];
            g_row_valid[m] = 1;
        } else {
            g_row_nll[m] = 0.0f;
            g_row_valid[m] = 0;
        }
    }
}

// ---------------- kernel 4: final reduction ----------------
__global__ __launch_bounds__(256) void finalize_kernel(float* __restrict__ out) {
    __shared__ float ssum[256];
    __shared__ int   scnt[256];
    const int tid = threadIdx.x;
    float s = 0.0f; int c = 0;
    for (int i = tid; i < M_; i += 256) { s += g_row_nll[i]; c += g_row_valid[i]; }
    ssum[tid] = s; scnt[tid] = c;
    __syncthreads();
    for (int st = 128; st > 0; st >>= 1) {
        if (tid < st) { ssum[tid] += ssum[tid + st]; scnt[tid] += scnt[tid + st]; }
        __syncthreads();
    }
    if (tid == 0) {
        int n = scnt[0] > 0 ? scnt[0] : 1;
        out[0] = ssum[0] / (float)n;
    }
}

// ---------------- launch ----------------
extern "C" void kernel_launch(void* const* d_in, const int* in_sizes, int n_in,
                              void* d_out, int out_size) {
    const float* feats  = (const float*)d_in[0];
    const float* Wmat   = (const float*)d_in[1];
    const float* bias   = (const float*)d_in[2];
    const int*   target = (const int*)d_in[4];
    const int*   lens   = (const int*)d_in[5];

    cudaFuncSetAttribute(gemm_kernel, cudaFuncAttributeMaxDynamicSharedMemorySize, SMEM_BYTES);

    prep_kernel<<<M_ + CONVW_BLOCKS, 256>>>(feats, lens, Wmat);

    dim3 grid(NPAD / BN, M_ / BM, SPLITS);   // (8, 8, 4) = 256 CTAs
    gemm_kernel<<<grid, 256, SMEM_BYTES>>>();

    nll_kernel<<<M_, 256>>>(bias, target);
    finalize_kernel<<<1, 256>>>((float*)d_out);
}

// round 11
// speedup vs baseline: 7.0787x; 1.0616x over previous
#include <cuda_runtime.h>
#include <cuda_bf16.h>
#include <cuda_fp8.h>
#include <math.h>
#include <cstdint>
#include <cstddef>

// Problem constants
#define B_    16
#define NT_   64
#define T_    8
#define D_    25088
#define C_    1000
#define M_    (B_ * NT_)   // 1024
#define NPAD  1024
#define K_    D_

// FP8 scaling
#define SCALE_A  64.0f
#define SCALE_W  2048.0f
#define INV_SCALE (1.0f / (SCALE_A * SCALE_W))

// GEMM tiling (fp8 mma.sync m16n8k32) + bulk-copy pipeline
#define BM     128
#define BN     128
#define BKK    128             // fp8 elems (bytes) per K-chunk
#define STAGES 3
#define SPLITS 4
#define KSPLIT (K_ / SPLITS)   // 6272
#define NIT    (KSPLIT / BKK)  // 49
#define NKC    (K_ / BKK)      // 196 K-chunks total
#define BLK    16384           // one [128 rows x 128 B] block
#define STAGE_BYTES (2 * BLK)  // A block + B block = 32768
#define SMEM_DATA   1024
#define SMEM_TOTAL  (SMEM_DATA + STAGES * STAGE_BYTES)   // 99328

#define CONVW_BLOCKS 1184

// ---------------- scratch (blocked, pre-swizzled fp8) ----------------
// layout: [tile][kc][row][128B], byte b stored at (b ^ ((row&7)*16))
__device__ __align__(1024) uint8_t g_AB[(size_t)(M_ / 128) * NKC * BLK];    // 25.7 MB
__device__ __align__(1024) uint8_t g_WB[(size_t)(NPAD / 128) * NKC * BLK];  // 25.7 MB
__device__ float g_part[(size_t)SPLITS * M_ * NPAD];    // 16 MB
__device__ float g_row_nll[M_];
__device__ int   g_row_valid[M_];

__device__ __forceinline__ uint8_t to_e4m3(float v) {
    return (uint8_t)__nv_cvt_float_to_fp8(v, __NV_SATFINITE, __NV_E4M3);
}

// ---------------- kernel 1: fused (pool -> fp8 blocked) + (W -> fp8 blocked) ----
__global__ __launch_bounds__(256) void prep_kernel(const float* __restrict__ feats,
                                                   const int* __restrict__ lens,
                                                   const float* __restrict__ W) {
    if (blockIdx.x < M_) {
        const int m = blockIdx.x;
        const int b = m / NT_;
        const int len = lens[b];
        const float inv = SCALE_A / (float)len;

        const float4* base = (const float4*)(feats + (size_t)m * T_ * D_);
        const int row = m & 127;
        const int mt  = m >> 7;
        const uint32_t rkey = (uint32_t)((row & 7) << 4);
        uint8_t* tile0 = g_AB + (size_t)mt * NKC * BLK;
        const int nv = D_ / 4;

        for (int i = threadIdx.x; i < nv; i += blockDim.x) {
            float4 acc = make_float4(0.f, 0.f, 0.f, 0.f);
            #pragma unroll
            for (int t = 0; t < T_; ++t) {
                if (t < len) {
                    float4 v = base[(size_t)t * (D_ / 4) + i];
                    acc.x += v.x; acc.y += v.y; acc.z += v.z; acc.w += v.w;
                }
            }
            uchar4 o;
            o.x = to_e4m3(acc.x * inv);
            o.y = to_e4m3(acc.y * inv);
            o.z = to_e4m3(acc.z * inv);
            o.w = to_e4m3(acc.w * inv);
            const int kc   = i >> 5;              // (i*4)/128
            const int bby  = (i & 31) * 4;        // byte within 128
            uint8_t* dst = tile0 + (size_t)kc * BLK + (row << 7) + ((uint32_t)bby ^ rkey);
            *(uchar4*)dst = o;
        }
    } else {
        // W (+ zero padding rows) -> blocked swizzled fp8
        const size_t nwords = (size_t)NPAD * K_ / 4;
        const size_t start = (size_t)(blockIdx.x - M_) * 256 + threadIdx.x;
        for (size_t i = start; i < nwords; i += (size_t)CONVW_BLOCKS * 256) {
            const int n = (int)(i / (K_ / 4));     // class row 0..1023
            const int w = (int)(i % (K_ / 4));     // word within row
            uchar4 o = make_uchar4(0, 0, 0, 0);
            if (n < C_) {
                float4 v = *(const float4*)(W + (size_t)n * K_ + w * 4);
                o.x = to_e4m3(v.x * SCALE_W);
                o.y = to_e4m3(v.y * SCALE_W);
                o.z = to_e4m3(v.z * SCALE_W);
                o.w = to_e4m3(v.w * SCALE_W);
            }
            const int row = n & 127;
            const int nt  = n >> 7;
            const int kc  = w >> 5;
            const int bby = (w & 31) * 4;
            const uint32_t rkey = (uint32_t)((row & 7) << 4);
            uint8_t* dst = g_WB + ((size_t)nt * NKC + kc) * BLK + (row << 7) + ((uint32_t)bby ^ rkey);
            *(uchar4*)dst = o;
        }
    }
}

// ---------------- bulk copy + mbarrier helpers ----------------
__device__ __forceinline__ void bulk_ld(uint32_t smem_dst, const void* gsrc,
                                        uint32_t bytes, uint32_t mbar) {
    asm volatile(
        "cp.async.bulk.shared::cluster.global.mbarrier::complete_tx::bytes [%0], [%1], %2, [%3];"
        :: "r"(smem_dst), "l"(gsrc), "r"(bytes), "r"(mbar) : "memory");
}
__device__ __forceinline__ void mbar_init(uint32_t mbar, uint32_t cnt) {
    asm volatile("mbarrier.init.shared.b64 [%0], %1;" :: "r"(mbar), "r"(cnt) : "memory");
}
__device__ __forceinline__ void mbar_expect_tx(uint32_t mbar, uint32_t bytes) {
    asm volatile("mbarrier.arrive.expect_tx.shared.b64 _, [%0], %1;"
                 :: "r"(mbar), "r"(bytes) : "memory");
}
__device__ __forceinline__ void mbar_wait(uint32_t mbar, uint32_t parity) {
    asm volatile(
        "{\n\t.reg .pred P1;\n\t"
        "WL_%=:\n\t"
        "mbarrier.try_wait.parity.acquire.cta.shared::cta.b64 P1, [%0], %1, 0x989680;\n\t"
        "@P1 bra.uni WD_%=;\n\t"
        "bra.uni WL_%=;\n\t"
        "WD_%=:\n\t}"
        :: "r"(mbar), "r"(parity) : "memory");
}

__device__ __forceinline__ void mma_e4m3(float* d, const uint32_t* a, const uint32_t* b) {
    asm volatile(
        "mma.sync.aligned.m16n8k32.row.col.f32.e4m3.e4m3.f32 "
        "{%0,%1,%2,%3}, {%4,%5,%6,%7}, {%8,%9}, {%0,%1,%2,%3};"
        : "+f"(d[0]), "+f"(d[1]), "+f"(d[2]), "+f"(d[3])
        : "r"(a[0]), "r"(a[1]), "r"(a[2]), "r"(a[3]), "r"(b[0]), "r"(b[1]));
}

__device__ __forceinline__ uint32_t smem_u32(const void* p) {
    uint32_t a;
    asm("{ .reg .u64 t; cvta.to.shared.u64 t, %1; cvt.u32.u64 %0, t; }" : "=r"(a) : "l"(p));
    return a;
}

// ---------------- kernel 2: fp8 mma GEMM, bulk-copy pipeline ----------------
__global__ __launch_bounds__(256, 2) void gemm_kernel() {
    extern __shared__ uint8_t sh[];
    const uint32_t smem_base = smem_u32(sh);

    const int bn    = blockIdx.x * BN;
    const int bm    = blockIdx.y * BM;
    const int split = blockIdx.z;
    const int kc0   = split * NIT;       // first K-chunk index for this split
    const int tid   = threadIdx.x;       // 256 threads, 8 warps
    const int warp  = tid >> 5;
    const int lane  = tid & 31;
    const int q     = lane >> 2;         // 0..7
    const int r4    = (lane & 3) * 4;
    const int wm    = (warp & 3) * 32;   // 4 warps along M
    const int wn    = (warp >> 2) * 64;  // 2 warps along N

    const uint8_t* Asrc = g_AB + (size_t)(bm >> 7) * NKC * BLK;   // + kc*BLK
    const uint8_t* Bsrc = g_WB + (size_t)(bn >> 7) * NKC * BLK;

    float acc[2][8][4];
    #pragma unroll
    for (int i = 0; i < 2; ++i)
        #pragma unroll
        for (int j = 0; j < 8; ++j)
            #pragma unroll
            for (int e = 0; e < 4; ++e)
                acc[i][j][e] = 0.0f;

    // mbarriers at smem_base + 8*s; stage data at SMEM_DATA + s*STAGE_BYTES
    if (tid == 0) {
        #pragma unroll
        for (int s = 0; s < STAGES; ++s) mbar_init(smem_base + 8 * s, 1);
    }
    __syncthreads();

    if (tid == 0) {
        #pragma unroll
        for (int s = 0; s < STAGES; ++s) {
            const uint32_t mb = smem_base + 8 * s;
            const uint32_t sd = smem_base + SMEM_DATA + s * STAGE_BYTES;
            mbar_expect_tx(mb, STAGE_BYTES);
            bulk_ld(sd,       Asrc + (size_t)(kc0 + s) * BLK, BLK, mb);
            bulk_ld(sd + BLK, Bsrc + (size_t)(kc0 + s) * BLK, BLK, mb);
        }
    }

    for (int it = 0; it < NIT; ++it) {
        const int s = it % STAGES;
        mbar_wait(smem_base + 8 * s, (uint32_t)((it / STAGES) & 1));

        const uint8_t* As = sh + SMEM_DATA + s * STAGE_BYTES;
        const uint8_t* Bs = As + BLK;
        const uint32_t qk = (uint32_t)(q << 4);

        #pragma unroll
        for (int ks = 0; ks < 4; ++ks) {              // 4 k32 steps
            const uint32_t k0 = ((uint32_t)(ks * 32 + r4)) ^ qk;
            const uint32_t k1 = k0 ^ 16u;
            uint32_t a[2][4], b[8][2];
            #pragma unroll
            for (int i = 0; i < 2; ++i) {
                const uint8_t* p0 = As + ((wm + i * 16 + q) << 7);
                const uint8_t* p1 = p0 + (8 << 7);
                a[i][0] = *(const uint32_t*)(p0 + k0);
                a[i][1] = *(const uint32_t*)(p1 + k0);
                a[i][2] = *(const uint32_t*)(p0 + k1);
                a[i][3] = *(const uint32_t*)(p1 + k1);
            }
            #pragma unroll
            for (int j = 0; j < 8; ++j) {
                const uint8_t* nb = Bs + ((wn + j * 8 + q) << 7);
                b[j][0] = *(const uint32_t*)(nb + k0);
                b[j][1] = *(const uint32_t*)(nb + k1);
            }
            #pragma unroll
            for (int i = 0; i < 2; ++i)
                #pragma unroll
                for (int j = 0; j < 8; ++j)
                    mma_e4m3(acc[i][j], a[i], b[j]);
        }

        __syncthreads();   // all warps done reading stage s
        if (tid == 0 && it + STAGES < NIT) {
            const uint32_t mb = smem_base + 8 * s;
            const uint32_t sd = smem_base + SMEM_DATA + s * STAGE_BYTES;
            mbar_expect_tx(mb, STAGE_BYTES);
            bulk_ld(sd,       Asrc + (size_t)(kc0 + it + STAGES) * BLK, BLK, mb);
            bulk_ld(sd + BLK, Bsrc + (size_t)(kc0 + it + STAGES) * BLK, BLK, mb);
        }
    }

    // epilogue
    float* base = g_part + (size_t)split * M_ * NPAD;
    #pragma unroll
    for (int i = 0; i < 2; ++i) {
        const int row0 = bm + wm + i * 16 + q;
        #pragma unroll
        for (int j = 0; j < 8; ++j) {
            const int col = bn + wn + j * 8 + (lane & 3) * 2;
            *(float2*)(base + (size_t)row0 * NPAD + col)       = make_float2(acc[i][j][0], acc[i][j][1]);
            *(float2*)(base + (size_t)(row0 + 8) * NPAD + col) = make_float2(acc[i][j][2], acc[i][j][3]);
        }
    }
}

// ---------------- kernel 3: fused split-K reduce + dequant + log-softmax NLL ----
__global__ __launch_bounds__(256) void nll_kernel(const float* __restrict__ bias,
                                                  const int* __restrict__ labels) {
    const int m = blockIdx.x;
    const int tid = threadIdx.x;
    const int lbl = labels[m];

    __shared__ float row[NPAD];
    __shared__ float red[256];

    for (int c = tid; c < C_; c += 256) {
        float v = 0.0f;
        #pragma unroll
        for (int s = 0; s < SPLITS; ++s)
            v += g_part[(size_t)s * M_ * NPAD + (size_t)m * NPAD + c];
        row[c] = v * INV_SCALE + bias[c];
    }
    __syncthreads();

    float mx = -INFINITY;
    for (int c = tid; c < C_; c += 256) mx = fmaxf(mx, row[c]);
    red[tid] = mx;
    __syncthreads();
    for (int s = 128; s > 0; s >>= 1) {
        if (tid < s) red[tid] = fmaxf(red[tid], red[tid + s]);
        __syncthreads();
    }
    const float smax = red[0];
    __syncthreads();

    float sum = 0.0f;
    for (int c = tid; c < C_; c += 256) sum += __expf(row[c] - smax);
    red[tid] = sum;
    __syncthreads();
    for (int s = 128; s > 0; s >>= 1) {
        if (tid < s) red[tid] += red[tid + s];
        __syncthreads();
    }

    if (tid == 0) {
        if (lbl >= 0) {
            g_row_nll[m] = logf(red[0]) + smax - row[lbl];
            g_row_valid[m] = 1;
        } else {
            g_row_nll[m] = 0.0f;
            g_row_valid[m] = 0;
        }
    }
}

// ---------------- kernel 4: final reduction ----------------
__global__ __launch_bounds__(256) void finalize_kernel(float* __restrict__ out) {
    __shared__ float ssum[256];
    __shared__ int   scnt[256];
    const int tid = threadIdx.x;
    float s = 0.0f; int c = 0;
    for (int i = tid; i < M_; i += 256) { s += g_row_nll[i]; c += g_row_valid[i]; }
    ssum[tid] = s; scnt[tid] = c;
    __syncthreads();
    for (int st = 128; st > 0; st >>= 1) {
        if (tid < st) { ssum[tid] += ssum[tid + st]; scnt[tid] += scnt[tid + st]; }
        __syncthreads();
    }
    if (tid == 0) {
        int n = scnt[0] > 0 ? scnt[0] : 1;
        out[0] = ssum[0] / (float)n;
    }
}

// ---------------- launch ----------------
extern "C" void kernel_launch(void* const* d_in, const int* in_sizes, int n_in,
                              void* d_out, int out_size) {
    const float* feats  = (const float*)d_in[0];
    const float* Wmat   = (const float*)d_in[1];
    const float* bias   = (const float*)d_in[2];
    const int*   target = (const int*)d_in[4];
    const int*   lens   = (const int*)d_in[5];

    cudaFuncSetAttribute(gemm_kernel, cudaFuncAttributeMaxDynamicSharedMemorySize, SMEM_TOTAL);

    prep_kernel<<<M_ + CONVW_BLOCKS, 256>>>(feats, lens, Wmat);

    dim3 grid(NPAD / BN, M_ / BM, SPLITS);   // (8, 8, 4) = 256 CTAs
    gemm_kernel<<<grid, 256, SMEM_TOTAL>>>();

    nll_kernel<<<M_, 256>>>(bias, target);
    finalize_kernel<<<1, 256>>>((float*)d_out);
}